// round 14
// baseline (speedup 1.0000x reference)
#include <cuda_runtime.h>
#include <cuda_bf16.h>
#include <math.h>
#include <stdint.h>

#define Bb   64
#define Tt   256
#define INd  512
#define Hd   1024
#define OUTd 512
#define G4   (4*Hd)        // 4096
#define Mrows (Bb*Tt)      // 16384

#define NBLK 128           // persistent blocks; each owns 8 hidden cols (x4 gates = N=32)
#define NJJ  8             // hidden cols per block
#define NKS  64            // k16 steps (K=1024)

// ---------------- scratch (device globals) ----------------
__device__ float g_xp[(size_t)Mrows * G4];          // [B*T, 4H]
__device__ __nv_bfloat16 g_xsh[(size_t)Mrows * INd];  // xs hi split
__device__ __nv_bfloat16 g_xsl[(size_t)Mrows * INd];  // xs lo split
__device__ __nv_bfloat16 g_hsh[(size_t)Mrows * Hd]; // hs hi split
__device__ __nv_bfloat16 g_hsl[(size_t)Mrows * Hd]; // hs lo split
// h ping-pong, PRE-SWIZZLED panel tiles: [ping][split][16 panels x 8192B]
__device__ __align__(16) char g_hT[2][2][16 * 8192];
__device__ unsigned g_bar;                          // grid barrier counter
// Wh pre-scattered into HMMA B-fragment order (recurrence):
__device__ uint4 g_Bfh[(size_t)NBLK * NKS * 2 * 32];
__device__ uint4 g_Bfl[(size_t)NBLK * NKS * 2 * 32];
// Wi / Wo fragment arrays
#define WI_CG (G4/32)      // 128
#define WI_KS (INd/16)     // 32
#define WO_CG (OUTd/32)    // 16
#define WO_KS (Hd/16)      // 64
__device__ uint4 g_WiFh[(size_t)WI_CG * WI_KS * 32 * 2];
__device__ uint4 g_WiFl[(size_t)WI_CG * WI_KS * 32 * 2];
__device__ uint4 g_WoFh[(size_t)WO_CG * WO_KS * 32 * 2];
__device__ uint4 g_WoFl[(size_t)WO_CG * WO_KS * 32 * 2];

#define SW128(b) ((b) ^ (((b) >> 3) & 0x70))
#define BIDX(s, wx) ((((size_t)blk * NKS + (s)) * 2 + (wx)) * 32 + lane)

__device__ __forceinline__ uint32_t smem_u32(const void* p) {
    uint32_t a;
    asm("{ .reg .u64 t; cvta.to.shared.u64 t, %1; cvt.u32.u64 %0, t; }" : "=r"(a) : "l"(p));
    return a;
}
__device__ __forceinline__ void ldmatrix_x4(uint32_t* r, uint32_t addr) {
    asm volatile("ldmatrix.sync.aligned.m8n8.x4.shared.b16 {%0,%1,%2,%3}, [%4];"
                 : "=r"(r[0]), "=r"(r[1]), "=r"(r[2]), "=r"(r[3]) : "r"(addr));
}
__device__ __forceinline__ void mma_bf16(float* c, const uint32_t* a,
                                         uint32_t b0, uint32_t b1) {
    asm volatile(
        "mma.sync.aligned.m16n8k16.row.col.f32.bf16.bf16.f32 "
        "{%0,%1,%2,%3}, {%4,%5,%6,%7}, {%8,%9}, {%0,%1,%2,%3};"
        : "+f"(c[0]), "+f"(c[1]), "+f"(c[2]), "+f"(c[3])
        : "r"(a[0]), "r"(a[1]), "r"(a[2]), "r"(a[3]), "r"(b0), "r"(b1));
}
__device__ __forceinline__ uint32_t pack_bf16(float x, float y) {
    __nv_bfloat162 v = __floats2bfloat162_rn(x, y);
    return *(uint32_t*)&v;
}
__device__ __forceinline__ void stg_cg_u16(void* p, uint16_t v) {
    asm volatile("st.global.cg.u16 [%0], %1;" :: "l"(p), "h"(v));
}
__device__ __forceinline__ float fsig(float x) {
    return __fdividef(1.f, 1.f + __expf(-x));
}
__device__ __forceinline__ float ftanh_f(float x) {
    return 1.f - __fdividef(2.f, __expf(2.f * x) + 1.f);
}
#define CP_ASYNC16(sm, gp) \
    asm volatile("cp.async.cg.shared.global [%0], [%1], 16;" :: "r"(sm), "l"(gp))
#define CP_COMMIT() asm volatile("cp.async.commit_group;" ::: "memory")
#define CP_WAIT(n)  asm volatile("cp.async.wait_group %0;" :: "n"(n) : "memory")

#define MBAR_INIT(mb) \
    asm volatile("mbarrier.init.shared.b64 [%0], %1;" :: "r"(mb), "r"(1u) : "memory")
#define MBAR_EXPECT_TX(mb, n) \
    asm volatile("mbarrier.arrive.expect_tx.shared.b64 _, [%0], %1;" :: "r"(mb), "r"(n) : "memory")
#define BULK_CP(dst, src, mb) \
    asm volatile("cp.async.bulk.shared::cta.global.mbarrier::complete_tx::bytes [%0], [%1], %2, [%3];" \
        :: "r"(dst), "l"(src), "r"(8192u), "r"(mb) : "memory")
#define FENCE_PROXY() asm volatile("fence.proxy.async.shared::cta;" ::: "memory")
#define MBAR_WAIT(mb, ph) do {                                                   \
    uint32_t _m = (mb), _p = (ph), _d;                                           \
    asm volatile("{ .reg .pred p; mbarrier.try_wait.parity.acquire.cta.shared::cta.b64 p, [%1], %2; selp.b32 %0,1,0,p; }" \
        : "=r"(_d) : "r"(_m), "r"(_p) : "memory");                               \
    if (!_d) {                                                                   \
        asm volatile("{ .reg .pred P1; WL_%=: mbarrier.try_wait.parity.acquire.cta.shared::cta.b64 P1, [%0], %1, 0x989680;" \
            " @P1 bra.uni WD_%=; bra.uni WL_%=; WD_%=: }" :: "r"(_m), "r"(_p) : "memory"); \
    }                                                                            \
} while (0)

// ---------------------------------------------------------------------------
__global__ void zero_state() {
    int i = blockIdx.x * blockDim.x + threadIdx.x;
    if (i == 0) g_bar = 0;
    // zero h ping 0 (both splits): 2 x 131072 B = 65536 uint32
    if (i < 65536) {
        int split = i >> 15, idx = i & 32767;
        ((uint32_t*)g_hT[0][split])[idx] = 0;
    }
}

__global__ __launch_bounds__(256) void split_xs(const float* __restrict__ xs) {
    size_t i = (size_t)blockIdx.x * blockDim.x + threadIdx.x;
    if (i < (size_t)Mrows * INd) {
        float v = xs[i];
        __nv_bfloat16 hi = __float2bfloat16_rn(v);
        g_xsh[i] = hi;
        g_xsl[i] = __float2bfloat16_rn(v - __bfloat162float(hi));
    }
}

// ---------------------------------------------------------------------------
__global__ __launch_bounds__(256) void prep_Bfrag(const float* __restrict__ Wh) {
    int gid = blockIdx.x * blockDim.x + threadIdx.x;
    int lane = gid & 31;
    int wx   = (gid >> 5) & 1;
    int ks   = (gid >> 6) & 63;
    int blk  = gid >> 12;

    uint32_t outh[4], outl[4];
    #pragma unroll
    for (int t2 = 0; t2 < 2; t2++) {
        int loc = wx * 16 + t2 * 8 + (lane >> 2);
        int g = loc >> 3, jj = loc & 7;
        int col = g * Hd + blk * NJJ + jj;
        int kb = ks * 16 + (lane & 3) * 2;
        float w0 = Wh[(size_t)(kb + 0) * G4 + col];
        float w1 = Wh[(size_t)(kb + 1) * G4 + col];
        float w8 = Wh[(size_t)(kb + 8) * G4 + col];
        float w9 = Wh[(size_t)(kb + 9) * G4 + col];
        float h0 = __bfloat162float(__float2bfloat16_rn(w0));
        float h1 = __bfloat162float(__float2bfloat16_rn(w1));
        float h8 = __bfloat162float(__float2bfloat16_rn(w8));
        float h9 = __bfloat162float(__float2bfloat16_rn(w9));
        outh[t2*2+0] = pack_bf16(h0, h1);
        outh[t2*2+1] = pack_bf16(h8, h9);
        outl[t2*2+0] = pack_bf16(w0 - h0, w1 - h1);
        outl[t2*2+1] = pack_bf16(w8 - h8, w9 - h9);
    }
    g_Bfh[gid] = make_uint4(outh[0], outh[1], outh[2], outh[3]);
    g_Bfl[gid] = make_uint4(outl[0], outl[1], outl[2], outl[3]);
}

// ---------------------------------------------------------------------------
__global__ __launch_bounds__(256)
void prep_Wfrag(const float* __restrict__ W, int N, int KS,
                uint4* __restrict__ outh_arr, uint4* __restrict__ outl_arr) {
    int gid = blockIdx.x * blockDim.x + threadIdx.x;
    int lane = gid & 31;
    int s    = (gid >> 5) % KS;
    int cg   = (gid >> 5) / KS;

    const int k0 = s * 16 + (lane & 3) * 2;
    #pragma unroll
    for (int j = 0; j < 2; j++) {
        uint32_t oh[4], ol[4];
        #pragma unroll
        for (int tt = 0; tt < 2; tt++) {
            int col = cg * 32 + (j * 2 + tt) * 8 + (lane >> 2);
            float w0 = W[(size_t)(k0 + 0) * N + col];
            float w1 = W[(size_t)(k0 + 1) * N + col];
            float w8 = W[(size_t)(k0 + 8) * N + col];
            float w9 = W[(size_t)(k0 + 9) * N + col];
            float h0 = __bfloat162float(__float2bfloat16_rn(w0));
            float h1 = __bfloat162float(__float2bfloat16_rn(w1));
            float h8 = __bfloat162float(__float2bfloat16_rn(w8));
            float h9 = __bfloat162float(__float2bfloat16_rn(w9));
            oh[tt*2+0] = pack_bf16(h0, h1);
            oh[tt*2+1] = pack_bf16(h8, h9);
            ol[tt*2+0] = pack_bf16(w0 - h0, w1 - h1);
            ol[tt*2+1] = pack_bf16(w8 - h8, w9 - h9);
        }
        outh_arr[(size_t)gid * 2 + j] = make_uint4(oh[0], oh[1], oh[2], oh[3]);
        outl_arr[(size_t)gid * 2 + j] = make_uint4(ol[0], ol[1], ol[2], ol[3]);
    }
}

// ---------------------------------------------------------------------------
// bf16x3-split HMMA GEMM (unchanged; projections).
template<int K>
__global__ __launch_bounds__(256)
void gemm_mma(const __nv_bfloat16* __restrict__ Ah,
              const __nv_bfloat16* __restrict__ Al,
              const uint4* __restrict__ BfH, const uint4* __restrict__ BfL,
              const float* __restrict__ bias, float* __restrict__ C, int N) {
    constexpr int KS = K / 16;
    constexpr int NC = K / 64;
    __shared__ __align__(16) char smA[2][2][16384];

    const int tid  = threadIdx.x;
    const int lane = tid & 31;
    const int wid  = tid >> 5;
    const int wy   = wid & 3;
    const int wn   = wid >> 2;
    const int rowBase = blockIdx.y * 128;
    const int colBase = blockIdx.x * 64;
    const int cg = blockIdx.x * 2 + wn;

    const uint32_t uA[2][2] = {
        { smem_u32(smA[0][0]), smem_u32(smA[0][1]) },
        { smem_u32(smA[1][0]), smem_u32(smA[1][1]) } };

    int rowi[4], qi[4]; uint32_t offi[4];
    #pragma unroll
    for (int i = 0; i < 4; i++) {
        int idx = i * 256 + tid;
        rowi[i] = idx >> 3; qi[i] = idx & 7;
        offi[i] = SW128((uint32_t)(rowi[i] * 128 + qi[i] * 16));
    }
    #define ISSUE_A(buf, kb)                                                     \
        do {                                                                     \
            _Pragma("unroll")                                                    \
            for (int i = 0; i < 4; i++) {                                        \
                CP_ASYNC16(uA[buf][0] + offi[i],                                 \
                    &Ah[(size_t)(rowBase + rowi[i]) * K + (kb) + qi[i] * 8]);    \
                CP_ASYNC16(uA[buf][1] + offi[i],                                 \
                    &Al[(size_t)(rowBase + rowi[i]) * K + (kb) + qi[i] * 8]);    \
            }                                                                    \
            CP_COMMIT();                                                         \
        } while (0)

    float acc[2][4][4] = {};
    const int lr = lane & 15, lch = (lane >> 4) * 8;

    const size_t bbase = ((size_t)cg * KS) * 64 + lane * 2;
    uint4 BH[2][2], BL[2][2];
    #pragma unroll
    for (int s = 0; s < 2; s++) {
        BH[s][0] = BfH[bbase + s * 64 + 0];
        BH[s][1] = BfH[bbase + s * 64 + 1];
        BL[s][0] = BfL[bbase + s * 64 + 0];
        BL[s][1] = BfL[bbase + s * 64 + 1];
    }

    ISSUE_A(0, 0);

    for (int kc = 0; kc < NC; kc++) {
        if (kc + 1 < NC) { ISSUE_A((kc + 1) & 1, (kc + 1) * 64); CP_WAIT(1); }
        else             { CP_WAIT(0); }
        __syncthreads();

        const uint32_t uh = uA[kc & 1][0], ul = uA[kc & 1][1];
        #pragma unroll
        for (int ks = 0; ks < 4; ks++) {
            const int s = kc * 4 + ks;
            uint4 bh0 = BH[ks & 1][0], bh1 = BH[ks & 1][1];
            uint4 bl0 = BL[ks & 1][0], bl1 = BL[ks & 1][1];
            if (s + 2 < KS) {
                BH[ks & 1][0] = BfH[bbase + (size_t)(s + 2) * 64 + 0];
                BH[ks & 1][1] = BfH[bbase + (size_t)(s + 2) * 64 + 1];
                BL[ks & 1][0] = BfL[bbase + (size_t)(s + 2) * 64 + 0];
                BL[ks & 1][1] = BfL[bbase + (size_t)(s + 2) * 64 + 1];
            }
            #pragma unroll
            for (int mt = 0; mt < 2; mt++) {
                const int lrow = wy * 32 + mt * 16 + lr;
                uint32_t offA = SW128((uint32_t)(lrow * 128 + (ks * 16 + lch) * 2));
                uint32_t ah[4], al[4];
                ldmatrix_x4(ah, uh + offA);
                ldmatrix_x4(al, ul + offA);

                mma_bf16(acc[mt][0], ah, bh0.x, bh0.y);
                mma_bf16(acc[mt][1], ah, bh0.z, bh0.w);
                mma_bf16(acc[mt][2], ah, bh1.x, bh1.y);
                mma_bf16(acc[mt][3], ah, bh1.z, bh1.w);
                mma_bf16(acc[mt][0], al, bh0.x, bh0.y);
                mma_bf16(acc[mt][1], al, bh0.z, bh0.w);
                mma_bf16(acc[mt][2], al, bh1.x, bh1.y);
                mma_bf16(acc[mt][3], al, bh1.z, bh1.w);
                mma_bf16(acc[mt][0], ah, bl0.x, bl0.y);
                mma_bf16(acc[mt][1], ah, bl0.z, bl0.w);
                mma_bf16(acc[mt][2], ah, bl1.x, bl1.y);
                mma_bf16(acc[mt][3], ah, bl1.z, bl1.w);
            }
        }
        __syncthreads();
    }

    const int r = lane >> 2, cc = (lane & 3) * 2;
    #pragma unroll
    for (int mt = 0; mt < 2; mt++) {
        const int m = rowBase + wy * 32 + mt * 16 + r;
        #pragma unroll
        for (int nt = 0; nt < 4; nt++) {
            const int n = colBase + wn * 32 + nt * 8 + cc;
            float b0 = bias[n], b1 = bias[n + 1];
            *(float2*)&C[(size_t)m * N + n] =
                make_float2(acc[mt][nt][0] + b0, acc[mt][nt][1] + b1);
            *(float2*)&C[(size_t)(m + 8) * N + n] =
                make_float2(acc[mt][nt][2] + b0, acc[mt][nt][3] + b1);
        }
    }
    #undef ISSUE_A
}

// ---------------------------------------------------------------------------
// Persistent HMMA LSTM v8: A staged via cp.async.bulk (4 x 8KB per chunk,
// thread-0 issued, mbarrier complete_tx) from PRE-SWIZZLED gmem h tiles.
// Kills ~2048 LDGSTS issues/chunk. Rest = R12 structure.
__global__ __launch_bounds__(256)
void lstm_persist() {
    extern __shared__ char dyn_sm[];
    char (*smA)[2][2][8192] = (char (*)[2][2][8192])dyn_sm;   // [buf3][split][panel]
    float (*Ds2)[64][32] = (float (*)[64][32])dyn_sm;         // aliases buf0
    const uint32_t mbb = smem_u32(dyn_sm + 98304);            // 3 mbarriers

    const int tid = threadIdx.x;
    const int lane = tid & 31;
    const int wid = tid >> 5;
    const int wy = wid & 3;          // M tile
    const int wk = wid >> 2;         // K half (panel)
    const int blk = blockIdx.x;
    const int jbase = blk * NJJ;

    const int lrow = wy * 16 + (lane & 15);
    const int lch  = (lane >> 4) * 8;

    uint32_t uP[3][2][2];  // [buf][split][panel]
    #pragma unroll
    for (int bu = 0; bu < 3; bu++)
        #pragma unroll
        for (int sp = 0; sp < 2; sp++)
            #pragma unroll
            for (int pp = 0; pp < 2; pp++)
                uP[bu][sp][pp] = smem_u32(smA[bu][sp][pp]);

    if (tid == 0) {
        MBAR_INIT(mbb + 0);
        MBAR_INIT(mbb + 8);
        MBAR_INIT(mbb + 16);
    }
    __syncthreads();

    // issue chunk c (panels 2c,2c+1 of both splits) into buffer buf
    #define ISSUE_CHUNK(buf, c, ping)                                            \
        do {                                                                     \
            const uint32_t mb = mbb + (buf) * 8;                                 \
            MBAR_EXPECT_TX(mb, 32768u);                                          \
            const char* s0 = g_hT[ping][0] + (size_t)(c) * 16384;                \
            const char* s1 = g_hT[ping][1] + (size_t)(c) * 16384;                \
            BULK_CP(uP[buf][0][0], s0,        mb);                               \
            BULK_CP(uP[buf][0][1], s0 + 8192, mb);                               \
            BULK_CP(uP[buf][1][0], s1,        mb);                               \
            BULK_CP(uP[buf][1][1], s1 + 8192, mb);                               \
        } while (0)

    const int ob0 = (tid * 2) >> 3,     oj0 = (tid * 2) & 7;
    const int ob1 = (tid * 2 + 1) >> 3, oj1 = (tid * 2 + 1) & 7;
    const int pnl = blk >> 3;                 // h panel this block's cols live in
    const int cjb = (blk & 7) * 8;            // col base within panel
    float c_r[2] = {0.f, 0.f};

    // prefetch xp for step 0
    float xg[2][4];
    #pragma unroll
    for (int g = 0; g < 4; g++) {
        xg[0][g] = g_xp[((size_t)ob0 * Tt + 0) * G4 + g * Hd + jbase + oj0];
        xg[1][g] = g_xp[((size_t)ob1 * Tt + 0) * G4 + g * Hd + jbase + oj1];
    }

    // B ring registers (step-invariant); init once, re-init pre-barrier
    uint4 BH0[2], BH1[2], BL0[2], BL1[2];
    #pragma unroll
    for (int u = 0; u < 2; u++) {
        const int s = wk * 4 + u;
        BH0[u] = g_Bfh[BIDX(s, 0)]; BH1[u] = g_Bfh[BIDX(s, 1)];
        BL0[u] = g_Bfl[BIDX(s, 0)]; BL1[u] = g_Bfl[BIDX(s, 1)];
    }

    for (int t = 0; t < Tt; t++) {
        const int ping = t & 1;
        const uint32_t tp = (uint32_t)(t & 1);

        if (tid == 0) {
            FENCE_PROXY();               // generic (Ds2/epilogue) -> async proxy
            ISSUE_CHUNK(0, 0, ping);
            ISSUE_CHUNK(1, 1, ping);
        }

        float acc[4][4] = {};   // [n-tile][frag]

        #pragma unroll
        for (int c = 0; c < 8; c++) {
            if (c + 2 < 8 && tid == 0) {
                FENCE_PROXY();
                ISSUE_CHUNK((c + 2) % 3, c + 2, ping);
            }
            // wait for this chunk's buffer; parity from fixed per-step schedule:
            // buf0 waits c=0,3,6; buf1 c=1,4,7; buf2 c=2,5 -> 3/3/2 per step
            {
                const uint32_t par = (c == 2) ? 0u : (c == 5) ? 1u
                                   : (c == 3 || c == 4) ? (tp ^ 1u) : tp;
                MBAR_WAIT(mbb + (c % 3) * 8, par);
            }

            const uint32_t uh = uP[c % 3][0][wk], ul = uP[c % 3][1][wk];
            #pragma unroll
            for (int ks = 0; ks < 4; ks++) {
                const int u = c * 4 + ks;
                uint4 bh0 = BH0[u & 1], bh1 = BH1[u & 1];
                uint4 bl0 = BL0[u & 1], bl1 = BL1[u & 1];
                if (u + 2 < 32) {
                    const int s2 = ((u + 2) >> 2) * 8 + wk * 4 + ((u + 2) & 3);
                    BH0[u & 1] = g_Bfh[BIDX(s2, 0)];
                    BH1[u & 1] = g_Bfh[BIDX(s2, 1)];
                    BL0[u & 1] = g_Bfl[BIDX(s2, 0)];
                    BL1[u & 1] = g_Bfl[BIDX(s2, 1)];
                }
                uint32_t offA = SW128((uint32_t)(lrow * 128 + (ks * 16 + lch) * 2));
                uint32_t ah[4], al[4];
                ldmatrix_x4(ah, uh + offA);
                ldmatrix_x4(al, ul + offA);

                mma_bf16(acc[0], ah, bh0.x, bh0.y);
                mma_bf16(acc[1], ah, bh0.z, bh0.w);
                mma_bf16(acc[2], ah, bh1.x, bh1.y);
                mma_bf16(acc[3], ah, bh1.z, bh1.w);
                mma_bf16(acc[0], al, bh0.x, bh0.y);
                mma_bf16(acc[1], al, bh0.z, bh0.w);
                mma_bf16(acc[2], al, bh1.x, bh1.y);
                mma_bf16(acc[3], al, bh1.z, bh1.w);
                mma_bf16(acc[0], ah, bl0.x, bl0.y);
                mma_bf16(acc[1], ah, bl0.z, bl0.w);
                mma_bf16(acc[2], ah, bl1.x, bl1.y);
                mma_bf16(acc[3], ah, bl1.z, bl1.w);
            }
            __syncthreads();   // all reads of this buffer done before reuse
        }

        // single-sync split-K reduction into Ds2 (aliased with buf0)
        const int r = lane >> 2, cc = (lane & 3) * 2;
        const int m0 = wy * 16;
        #pragma unroll
        for (int nt = 0; nt < 4; nt++) {
            Ds2[wk][m0 + r    ][nt * 8 + cc    ] = acc[nt][0];
            Ds2[wk][m0 + r    ][nt * 8 + cc + 1] = acc[nt][1];
            Ds2[wk][m0 + r + 8][nt * 8 + cc    ] = acc[nt][2];
            Ds2[wk][m0 + r + 8][nt * 8 + cc + 1] = acc[nt][3];
        }
        __syncthreads();

        // fused nonlinearity; h stores pre-swizzled into g_hT, hs kept linear
        #pragma unroll
        for (int u = 0; u < 2; u++) {
            const int b  = u ? ob1 : ob0;
            const int jj = u ? oj1 : oj0;
            float gi = Ds2[0][b][0*8 + jj] + Ds2[1][b][0*8 + jj] + xg[u][0];
            float gf = Ds2[0][b][1*8 + jj] + Ds2[1][b][1*8 + jj] + xg[u][1];
            float gg = Ds2[0][b][2*8 + jj] + Ds2[1][b][2*8 + jj] + xg[u][2];
            float go = Ds2[0][b][3*8 + jj] + Ds2[1][b][3*8 + jj] + xg[u][3];

            float si = fsig(gi);
            float sf = fsig(gf);
            float so = fsig(go);
            float tg = ftanh_f(gg);

            float cN = sf * c_r[u] + si * tg;
            c_r[u] = cN;
            float hN = so * ftanh_f(cN);

            __nv_bfloat16 hi = __float2bfloat16_rn(hN);
            __nv_bfloat16 lo = __float2bfloat16_rn(hN - __bfloat162float(hi));
            const uint32_t sw = SW128((uint32_t)(b * 128 + (cjb + jj) * 2));
            stg_cg_u16(g_hT[(t + 1) & 1][0] + (size_t)pnl * 8192 + sw, *(uint16_t*)&hi);
            stg_cg_u16(g_hT[(t + 1) & 1][1] + (size_t)pnl * 8192 + sw, *(uint16_t*)&lo);
            const size_t hsi = ((size_t)b * Tt + t) * Hd + jbase + jj;
            stg_cg_u16(&g_hsh[hsi], *(uint16_t*)&hi);
            stg_cg_u16(&g_hsl[hsi], *(uint16_t*)&lo);
        }

        // pre-barrier prefetches (independent of h(t+1)):
        if (t + 1 < Tt) {
            #pragma unroll
            for (int g = 0; g < 4; g++) {
                xg[0][g] = g_xp[((size_t)ob0 * Tt + t + 1) * G4 + g * Hd + jbase + oj0];
                xg[1][g] = g_xp[((size_t)ob1 * Tt + t + 1) * G4 + g * Hd + jbase + oj1];
            }
            #pragma unroll
            for (int u = 0; u < 2; u++) {
                const int s = wk * 4 + u;
                BH0[u] = g_Bfh[BIDX(s, 0)]; BH1[u] = g_Bfh[BIDX(s, 1)];
                BL0[u] = g_Bfl[BIDX(s, 0)]; BL1[u] = g_Bfl[BIDX(s, 1)];
            }
        }

        // grid barrier: atomic arrive, single volatile-load poller
        __syncthreads();
        if (tid == 0) {
            __threadfence();
            atomicAdd(&g_bar, 1u);
            const unsigned tgt = (unsigned)(t + 1) * (unsigned)NBLK;
            while (*(volatile unsigned*)&g_bar < tgt) { }
            __threadfence();
        }
        __syncthreads();
    }
    #undef ISSUE_CHUNK
}

// ---------------------------------------------------------------------------
extern "C" void kernel_launch(void* const* d_in, const int* in_sizes, int n_in,
                              void* d_out, int out_size) {
    const float* xs = (const float*)d_in[0];
    const float* Wi = (const float*)d_in[1];
    const float* Wh = (const float*)d_in[2];
    const float* b  = (const float*)d_in[3];
    const float* Wo = (const float*)d_in[4];
    const float* bo = (const float*)d_in[5];
    float* out = (float*)d_out;

    float* xp_p = nullptr;
    __nv_bfloat16 *xsh_p = nullptr, *xsl_p = nullptr, *hsh_p = nullptr, *hsl_p = nullptr;
    uint4 *wifh = nullptr, *wifl = nullptr, *wofh = nullptr, *wofl = nullptr;
    cudaGetSymbolAddress((void**)&xp_p, g_xp);
    cudaGetSymbolAddress((void**)&xsh_p, g_xsh);
    cudaGetSymbolAddress((void**)&xsl_p, g_xsl);
    cudaGetSymbolAddress((void**)&hsh_p, g_hsh);
    cudaGetSymbolAddress((void**)&hsl_p, g_hsl);
    cudaGetSymbolAddress((void**)&wifh, g_WiFh);
    cudaGetSymbolAddress((void**)&wifl, g_WiFl);
    cudaGetSymbolAddress((void**)&wofh, g_WoFh);
    cudaGetSymbolAddress((void**)&wofl, g_WoFl);

    const int lp_smem = 98304 + 64;   // 3 A bufs (Ds2 aliased) + 3 mbarriers
    cudaFuncSetAttribute(lstm_persist,
                         cudaFuncAttributeMaxDynamicSharedMemorySize, lp_smem);

    // 0) init + splits + fragment scatters
    zero_state<<<(65536 + 255) / 256, 256>>>();
    split_xs<<<(int)(((size_t)Mrows * INd + 255) / 256), 256>>>(xs);
    prep_Bfrag<<<(NBLK * NKS * 2 * 32) / 256, 256>>>(Wh);
    prep_Wfrag<<<(WI_CG * WI_KS * 32) / 256, 256>>>(Wi, G4, WI_KS, wifh, wifl);
    prep_Wfrag<<<(WO_CG * WO_KS * 32) / 256, 256>>>(Wo, OUTd, WO_KS, wofh, wofl);

    // 1) xp = xs @ Wi + b   (HMMA)
    {
        dim3 grid(G4 / 64, Mrows / 128);
        gemm_mma<INd><<<grid, 256>>>(xsh_p, xsl_p, wifh, wifl, b, xp_p, G4);
    }

    // 2) recurrence: one persistent launch
    lstm_persist<<<NBLK, 256, lp_smem>>>();

    // 3) logits = hs @ Wo + bo   (HMMA)
    {
        dim3 grid(OUTd / 64, Mrows / 128);
        gemm_mma<Hd><<<grid, 256>>>(hsh_p, hsl_p, wofh, wofl, bo, out, OUTd);
    }
}

// round 15
// speedup vs baseline: 1.0859x; 1.0859x over previous
#include <cuda_runtime.h>
#include <cuda_bf16.h>
#include <math.h>
#include <stdint.h>

#define Bb   64
#define Tt   256
#define INd  512
#define Hd   1024
#define OUTd 512
#define G4   (4*Hd)        // 4096
#define Mrows (Bb*Tt)      // 16384

#define NBLK 128           // persistent blocks; each owns 8 hidden cols (x4 gates = N=32)
#define NJJ  8             // hidden cols per block
#define NKS  64            // k16 steps (K=1024)

// ---------------- scratch (device globals) ----------------
__device__ float g_xp[(size_t)Mrows * G4];          // [B*T, 4H]
__device__ __nv_bfloat16 g_xsh[(size_t)Mrows * INd];  // xs hi split
__device__ __nv_bfloat16 g_xsl[(size_t)Mrows * INd];  // xs lo split
__device__ __nv_bfloat16 g_hsh[(size_t)Mrows * Hd]; // hs hi split
__device__ __nv_bfloat16 g_hsl[(size_t)Mrows * Hd]; // hs lo split
__device__ __nv_bfloat16 g_hh[2][Bb * Hd];          // h hi (ping-pong)
__device__ __nv_bfloat16 g_hl[2][Bb * Hd];          // h lo
__device__ unsigned g_bar;                          // grid barrier counter
// Wh pre-scattered into HMMA B-fragment order (recurrence):
__device__ uint4 g_Bfh[(size_t)NBLK * NKS * 2 * 32];
__device__ uint4 g_Bfl[(size_t)NBLK * NKS * 2 * 32];
// Wi / Wo fragment arrays
#define WI_CG (G4/32)      // 128
#define WI_KS (INd/16)     // 32
#define WO_CG (OUTd/32)    // 16
#define WO_KS (Hd/16)      // 64
__device__ uint4 g_WiFh[(size_t)WI_CG * WI_KS * 32 * 2];
__device__ uint4 g_WiFl[(size_t)WI_CG * WI_KS * 32 * 2];
__device__ uint4 g_WoFh[(size_t)WO_CG * WO_KS * 32 * 2];
__device__ uint4 g_WoFl[(size_t)WO_CG * WO_KS * 32 * 2];

#define SW128(b) ((b) ^ (((b) >> 3) & 0x70))
#define BIDX(s, wx) ((((size_t)blk * NKS + (s)) * 2 + (wx)) * 32 + lane)

__device__ __forceinline__ uint32_t smem_u32(const void* p) {
    uint32_t a;
    asm("{ .reg .u64 t; cvta.to.shared.u64 t, %1; cvt.u32.u64 %0, t; }" : "=r"(a) : "l"(p));
    return a;
}
__device__ __forceinline__ void ldmatrix_x4(uint32_t* r, uint32_t addr) {
    asm volatile("ldmatrix.sync.aligned.m8n8.x4.shared.b16 {%0,%1,%2,%3}, [%4];"
                 : "=r"(r[0]), "=r"(r[1]), "=r"(r[2]), "=r"(r[3]) : "r"(addr));
}
__device__ __forceinline__ void mma_bf16(float* c, const uint32_t* a,
                                         uint32_t b0, uint32_t b1) {
    asm volatile(
        "mma.sync.aligned.m16n8k16.row.col.f32.bf16.bf16.f32 "
        "{%0,%1,%2,%3}, {%4,%5,%6,%7}, {%8,%9}, {%0,%1,%2,%3};"
        : "+f"(c[0]), "+f"(c[1]), "+f"(c[2]), "+f"(c[3])
        : "r"(a[0]), "r"(a[1]), "r"(a[2]), "r"(a[3]), "r"(b0), "r"(b1));
}
__device__ __forceinline__ uint32_t pack_bf16(float x, float y) {
    __nv_bfloat162 v = __floats2bfloat162_rn(x, y);
    return *(uint32_t*)&v;
}
__device__ __forceinline__ void stg_cg_u16(void* p, uint16_t v) {
    asm volatile("st.global.cg.u16 [%0], %1;" :: "l"(p), "h"(v));
}
__device__ __forceinline__ float fsig(float x) {
    return __fdividef(1.f, 1.f + __expf(-x));
}
__device__ __forceinline__ float ftanh_f(float x) {
    return 1.f - __fdividef(2.f, __expf(2.f * x) + 1.f);
}
#define CP_ASYNC16(sm, gp) \
    asm volatile("cp.async.cg.shared.global [%0], [%1], 16;" :: "r"(sm), "l"(gp))
#define CP_COMMIT() asm volatile("cp.async.commit_group;" ::: "memory")
#define CP_WAIT(n)  asm volatile("cp.async.wait_group %0;" :: "n"(n) : "memory")

// ---------------------------------------------------------------------------
__global__ void zero_state() {
    int i = blockIdx.x * blockDim.x + threadIdx.x;
    if (i == 0) g_bar = 0;
    if (i < Bb * Hd) {
        g_hh[0][i] = __float2bfloat16(0.f);
        g_hl[0][i] = __float2bfloat16(0.f);
    }
}

__global__ __launch_bounds__(256) void split_xs(const float* __restrict__ xs) {
    size_t i = (size_t)blockIdx.x * blockDim.x + threadIdx.x;
    if (i < (size_t)Mrows * INd) {
        float v = xs[i];
        __nv_bfloat16 hi = __float2bfloat16_rn(v);
        g_xsh[i] = hi;
        g_xsl[i] = __float2bfloat16_rn(v - __bfloat162float(hi));
    }
}

// ---------------------------------------------------------------------------
__global__ __launch_bounds__(256) void prep_Bfrag(const float* __restrict__ Wh) {
    int gid = blockIdx.x * blockDim.x + threadIdx.x;
    int lane = gid & 31;
    int wx   = (gid >> 5) & 1;
    int ks   = (gid >> 6) & 63;
    int blk  = gid >> 12;

    uint32_t outh[4], outl[4];
    #pragma unroll
    for (int t2 = 0; t2 < 2; t2++) {
        int loc = wx * 16 + t2 * 8 + (lane >> 2);
        int g = loc >> 3, jj = loc & 7;
        int col = g * Hd + blk * NJJ + jj;
        int kb = ks * 16 + (lane & 3) * 2;
        float w0 = Wh[(size_t)(kb + 0) * G4 + col];
        float w1 = Wh[(size_t)(kb + 1) * G4 + col];
        float w8 = Wh[(size_t)(kb + 8) * G4 + col];
        float w9 = Wh[(size_t)(kb + 9) * G4 + col];
        float h0 = __bfloat162float(__float2bfloat16_rn(w0));
        float h1 = __bfloat162float(__float2bfloat16_rn(w1));
        float h8 = __bfloat162float(__float2bfloat16_rn(w8));
        float h9 = __bfloat162float(__float2bfloat16_rn(w9));
        outh[t2*2+0] = pack_bf16(h0, h1);
        outh[t2*2+1] = pack_bf16(h8, h9);
        outl[t2*2+0] = pack_bf16(w0 - h0, w1 - h1);
        outl[t2*2+1] = pack_bf16(w8 - h8, w9 - h9);
    }
    g_Bfh[gid] = make_uint4(outh[0], outh[1], outh[2], outh[3]);
    g_Bfl[gid] = make_uint4(outl[0], outl[1], outl[2], outl[3]);
}

// ---------------------------------------------------------------------------
__global__ __launch_bounds__(256)
void prep_Wfrag(const float* __restrict__ W, int N, int KS,
                uint4* __restrict__ outh_arr, uint4* __restrict__ outl_arr) {
    int gid = blockIdx.x * blockDim.x + threadIdx.x;
    int lane = gid & 31;
    int s    = (gid >> 5) % KS;
    int cg   = (gid >> 5) / KS;

    const int k0 = s * 16 + (lane & 3) * 2;
    #pragma unroll
    for (int j = 0; j < 2; j++) {
        uint32_t oh[4], ol[4];
        #pragma unroll
        for (int tt = 0; tt < 2; tt++) {
            int col = cg * 32 + (j * 2 + tt) * 8 + (lane >> 2);
            float w0 = W[(size_t)(k0 + 0) * N + col];
            float w1 = W[(size_t)(k0 + 1) * N + col];
            float w8 = W[(size_t)(k0 + 8) * N + col];
            float w9 = W[(size_t)(k0 + 9) * N + col];
            float h0 = __bfloat162float(__float2bfloat16_rn(w0));
            float h1 = __bfloat162float(__float2bfloat16_rn(w1));
            float h8 = __bfloat162float(__float2bfloat16_rn(w8));
            float h9 = __bfloat162float(__float2bfloat16_rn(w9));
            oh[tt*2+0] = pack_bf16(h0, h1);
            oh[tt*2+1] = pack_bf16(h8, h9);
            ol[tt*2+0] = pack_bf16(w0 - h0, w1 - h1);
            ol[tt*2+1] = pack_bf16(w8 - h8, w9 - h9);
        }
        outh_arr[(size_t)gid * 2 + j] = make_uint4(oh[0], oh[1], oh[2], oh[3]);
        outl_arr[(size_t)gid * 2 + j] = make_uint4(ol[0], ol[1], ol[2], ol[3]);
    }
}

// ---------------------------------------------------------------------------
// bf16x3-split HMMA GEMM (unchanged; projections).
template<int K>
__global__ __launch_bounds__(256)
void gemm_mma(const __nv_bfloat16* __restrict__ Ah,
              const __nv_bfloat16* __restrict__ Al,
              const uint4* __restrict__ BfH, const uint4* __restrict__ BfL,
              const float* __restrict__ bias, float* __restrict__ C, int N) {
    constexpr int KS = K / 16;
    constexpr int NC = K / 64;
    __shared__ __align__(16) char smA[2][2][16384];

    const int tid  = threadIdx.x;
    const int lane = tid & 31;
    const int wid  = tid >> 5;
    const int wy   = wid & 3;
    const int wn   = wid >> 2;
    const int rowBase = blockIdx.y * 128;
    const int colBase = blockIdx.x * 64;
    const int cg = blockIdx.x * 2 + wn;

    const uint32_t uA[2][2] = {
        { smem_u32(smA[0][0]), smem_u32(smA[0][1]) },
        { smem_u32(smA[1][0]), smem_u32(smA[1][1]) } };

    int rowi[4], qi[4]; uint32_t offi[4];
    #pragma unroll
    for (int i = 0; i < 4; i++) {
        int idx = i * 256 + tid;
        rowi[i] = idx >> 3; qi[i] = idx & 7;
        offi[i] = SW128((uint32_t)(rowi[i] * 128 + qi[i] * 16));
    }
    #define ISSUE_A(buf, kb)                                                     \
        do {                                                                     \
            _Pragma("unroll")                                                    \
            for (int i = 0; i < 4; i++) {                                        \
                CP_ASYNC16(uA[buf][0] + offi[i],                                 \
                    &Ah[(size_t)(rowBase + rowi[i]) * K + (kb) + qi[i] * 8]);    \
                CP_ASYNC16(uA[buf][1] + offi[i],                                 \
                    &Al[(size_t)(rowBase + rowi[i]) * K + (kb) + qi[i] * 8]);    \
            }                                                                    \
            CP_COMMIT();                                                         \
        } while (0)

    float acc[2][4][4] = {};
    const int lr = lane & 15, lch = (lane >> 4) * 8;

    const size_t bbase = ((size_t)cg * KS) * 64 + lane * 2;
    uint4 BH[2][2], BL[2][2];
    #pragma unroll
    for (int s = 0; s < 2; s++) {
        BH[s][0] = BfH[bbase + s * 64 + 0];
        BH[s][1] = BfH[bbase + s * 64 + 1];
        BL[s][0] = BfL[bbase + s * 64 + 0];
        BL[s][1] = BfL[bbase + s * 64 + 1];
    }

    ISSUE_A(0, 0);

    for (int kc = 0; kc < NC; kc++) {
        if (kc + 1 < NC) { ISSUE_A((kc + 1) & 1, (kc + 1) * 64); CP_WAIT(1); }
        else             { CP_WAIT(0); }
        __syncthreads();

        const uint32_t uh = uA[kc & 1][0], ul = uA[kc & 1][1];
        #pragma unroll
        for (int ks = 0; ks < 4; ks++) {
            const int s = kc * 4 + ks;
            uint4 bh0 = BH[ks & 1][0], bh1 = BH[ks & 1][1];
            uint4 bl0 = BL[ks & 1][0], bl1 = BL[ks & 1][1];
            if (s + 2 < KS) {
                BH[ks & 1][0] = BfH[bbase + (size_t)(s + 2) * 64 + 0];
                BH[ks & 1][1] = BfH[bbase + (size_t)(s + 2) * 64 + 1];
                BL[ks & 1][0] = BfL[bbase + (size_t)(s + 2) * 64 + 0];
                BL[ks & 1][1] = BfL[bbase + (size_t)(s + 2) * 64 + 1];
            }
            #pragma unroll
            for (int mt = 0; mt < 2; mt++) {
                const int lrow = wy * 32 + mt * 16 + lr;
                uint32_t offA = SW128((uint32_t)(lrow * 128 + (ks * 16 + lch) * 2));
                uint32_t ah[4], al[4];
                ldmatrix_x4(ah, uh + offA);
                ldmatrix_x4(al, ul + offA);

                mma_bf16(acc[mt][0], ah, bh0.x, bh0.y);
                mma_bf16(acc[mt][1], ah, bh0.z, bh0.w);
                mma_bf16(acc[mt][2], ah, bh1.x, bh1.y);
                mma_bf16(acc[mt][3], ah, bh1.z, bh1.w);
                mma_bf16(acc[mt][0], al, bh0.x, bh0.y);
                mma_bf16(acc[mt][1], al, bh0.z, bh0.w);
                mma_bf16(acc[mt][2], al, bh1.x, bh1.y);
                mma_bf16(acc[mt][3], al, bh1.z, bh1.w);
                mma_bf16(acc[mt][0], ah, bl0.x, bl0.y);
                mma_bf16(acc[mt][1], ah, bl0.z, bl0.w);
                mma_bf16(acc[mt][2], ah, bl1.x, bl1.y);
                mma_bf16(acc[mt][3], ah, bl1.z, bl1.w);
            }
        }
        __syncthreads();
    }

    const int r = lane >> 2, cc = (lane & 3) * 2;
    #pragma unroll
    for (int mt = 0; mt < 2; mt++) {
        const int m = rowBase + wy * 32 + mt * 16 + r;
        #pragma unroll
        for (int nt = 0; nt < 4; nt++) {
            const int n = colBase + wn * 32 + nt * 8 + cc;
            float b0 = bias[n], b1 = bias[n + 1];
            *(float2*)&C[(size_t)m * N + n] =
                make_float2(acc[mt][nt][0] + b0, acc[mt][nt][1] + b1);
            *(float2*)&C[(size_t)(m + 8) * N + n] =
                make_float2(acc[mt][nt][2] + b0, acc[mt][nt][3] + b1);
        }
    }
    #undef ISSUE_A
}

// ---------------------------------------------------------------------------
// Persistent HMMA LSTM v9: K=256 chunks (4/step, 3 x 64KB buffers) -> half the
// per-chunk serial tails vs R12. LDGSTS staging (R12 style), Ds2 aliased onto
// buf1, counter barrier, pre-barrier prefetches, fast-intrinsic epilogue.
__global__ __launch_bounds__(256)
void lstm_persist() {
    extern __shared__ char dyn_sm[];
    // A: [buf3][split2][4 panels x 8192B] = 3 x 65536 = 196608 bytes.
    // Ds2 aliases buf1 (free after chunk 1; chunks 2,3 use buf2,buf0).
    float (*Ds2)[64][32] = (float (*)[64][32])(dyn_sm + 65536);

    const int tid = threadIdx.x;
    const int lane = tid & 31;
    const int wid = tid >> 5;
    const int wy = wid & 3;          // M tile
    const int wk = wid >> 2;         // K half of each chunk (2 panels)
    const int blk = blockIdx.x;
    const int jbase = blk * NJJ;

    const int lrow = wy * 16 + (lane & 15);
    const int lch  = (lane >> 4) * 8;

    // A staging: per K=256 chunk, 4096 uint4 total; thread does 8 per split.
    uint32_t off_sm[8]; int off_g[8];
    #pragma unroll
    for (int i = 0; i < 8; i++) {
        int idx = i * 256 + tid;          // 0..2047
        int panel = idx >> 9;             // 0..3
        int inner = idx & 511;
        int row = inner >> 3, q = inner & 7;
        off_sm[i] = (uint32_t)(panel * 8192) + SW128((uint32_t)(row * 128 + q * 16));
        off_g[i]  = row * Hd + panel * 64 + q * 8;
    }

    uint32_t uB[3][2];  // [buf][split] base
    #pragma unroll
    for (int bu = 0; bu < 3; bu++)
        #pragma unroll
        for (int sp = 0; sp < 2; sp++)
            uB[bu][sp] = smem_u32(dyn_sm + bu * 65536 + sp * 32768);

    #define ISSUE_H(buf, kb)                                                     \
        do {                                                                     \
            _Pragma("unroll")                                                    \
            for (int i = 0; i < 8; i++) {                                        \
                CP_ASYNC16(uB[buf][0] + off_sm[i], &hh[off_g[i] + (kb)]);        \
                CP_ASYNC16(uB[buf][1] + off_sm[i], &hl[off_g[i] + (kb)]);        \
            }                                                                    \
            CP_COMMIT();                                                         \
        } while (0)

    const int ob0 = (tid * 2) >> 3,     oj0 = (tid * 2) & 7;
    const int ob1 = (tid * 2 + 1) >> 3, oj1 = (tid * 2 + 1) & 7;
    float c_r[2] = {0.f, 0.f};

    // prefetch xp for step 0
    float xg[2][4];
    #pragma unroll
    for (int g = 0; g < 4; g++) {
        xg[0][g] = g_xp[((size_t)ob0 * Tt + 0) * G4 + g * Hd + jbase + oj0];
        xg[1][g] = g_xp[((size_t)ob1 * Tt + 0) * G4 + g * Hd + jbase + oj1];
    }

    // B ring (2-deep). Per-warp iteration u = c*8 + j;
    // s(u) = (u>>3)*16 + wk*8 + (u&7), covering all 64 k16-steps across wk.
    uint4 BH0[2], BH1[2], BL0[2], BL1[2];
    #pragma unroll
    for (int u = 0; u < 2; u++) {
        const int s = wk * 8 + u;
        BH0[u] = g_Bfh[BIDX(s, 0)]; BH1[u] = g_Bfh[BIDX(s, 1)];
        BL0[u] = g_Bfl[BIDX(s, 0)]; BL1[u] = g_Bfl[BIDX(s, 1)];
    }

    for (int t = 0; t < Tt; t++) {
        const __nv_bfloat16* hh = g_hh[t & 1];
        const __nv_bfloat16* hl = g_hl[t & 1];

        // stage chunks 0 and 1 (3-buffer rotation)
        ISSUE_H(0, 0);
        ISSUE_H(1, 256);
        CP_WAIT(1);            // chunk 0 done
        __syncthreads();

        float acc[4][4] = {};   // [n-tile][frag]

        #pragma unroll
        for (int c = 0; c < 4; c++) {
            if (c + 2 < 4) ISSUE_H((c + 2) % 3, (c + 2) * 256);

            // warp wk consumes panels [2wk, 2wk+1] of this chunk
            const uint32_t uh = uB[c % 3][0] + (uint32_t)(wk * 16384);
            const uint32_t ul = uB[c % 3][1] + (uint32_t)(wk * 16384);

            #pragma unroll
            for (int j = 0; j < 8; j++) {
                const int u = c * 8 + j;
                uint4 bh0 = BH0[u & 1], bh1 = BH1[u & 1];
                uint4 bl0 = BL0[u & 1], bl1 = BL1[u & 1];
                if (u + 2 < 32) {
                    const int s2 = ((u + 2) >> 3) * 16 + wk * 8 + ((u + 2) & 7);
                    BH0[u & 1] = g_Bfh[BIDX(s2, 0)];
                    BH1[u & 1] = g_Bfh[BIDX(s2, 1)];
                    BL0[u & 1] = g_Bfl[BIDX(s2, 0)];
                    BL1[u & 1] = g_Bfl[BIDX(s2, 1)];
                }
                uint32_t offA = (uint32_t)((j >> 2) * 8192)
                              + SW128((uint32_t)(lrow * 128 + ((j & 3) * 16 + lch) * 2));
                uint32_t ah[4], al[4];
                ldmatrix_x4(ah, uh + offA);
                ldmatrix_x4(al, ul + offA);

                mma_bf16(acc[0], ah, bh0.x, bh0.y);
                mma_bf16(acc[1], ah, bh0.z, bh0.w);
                mma_bf16(acc[2], ah, bh1.x, bh1.y);
                mma_bf16(acc[3], ah, bh1.z, bh1.w);
                mma_bf16(acc[0], al, bh0.x, bh0.y);
                mma_bf16(acc[1], al, bh0.z, bh0.w);
                mma_bf16(acc[2], al, bh1.x, bh1.y);
                mma_bf16(acc[3], al, bh1.z, bh1.w);
                mma_bf16(acc[0], ah, bl0.x, bl0.y);
                mma_bf16(acc[1], ah, bl0.z, bl0.w);
                mma_bf16(acc[2], ah, bl1.x, bl1.y);
                mma_bf16(acc[3], ah, bl1.z, bl1.w);
            }

            if (c + 1 < 4) {
                if (c + 2 < 4) CP_WAIT(1);    // oldest pending (c+1) done
                else           CP_WAIT(0);
                __syncthreads();
            }
        }

        // split-K reduction into Ds2 (aliased with buf1 — free since chunk 1;
        // chunk 3 reads buf0, so concurrent writes here are conflict-free)
        const int r = lane >> 2, cc = (lane & 3) * 2;
        const int m0 = wy * 16;
        #pragma unroll
        for (int nt = 0; nt < 4; nt++) {
            Ds2[wk][m0 + r    ][nt * 8 + cc    ] = acc[nt][0];
            Ds2[wk][m0 + r    ][nt * 8 + cc + 1] = acc[nt][1];
            Ds2[wk][m0 + r + 8][nt * 8 + cc    ] = acc[nt][2];
            Ds2[wk][m0 + r + 8][nt * 8 + cc + 1] = acc[nt][3];
        }
        __syncthreads();

        // fused nonlinearity (xg prefetched, fast intrinsics); st.cg stores
        #pragma unroll
        for (int u = 0; u < 2; u++) {
            const int b  = u ? ob1 : ob0;
            const int jj = u ? oj1 : oj0;
            float gi = Ds2[0][b][0*8 + jj] + Ds2[1][b][0*8 + jj] + xg[u][0];
            float gf = Ds2[0][b][1*8 + jj] + Ds2[1][b][1*8 + jj] + xg[u][1];
            float gg = Ds2[0][b][2*8 + jj] + Ds2[1][b][2*8 + jj] + xg[u][2];
            float go = Ds2[0][b][3*8 + jj] + Ds2[1][b][3*8 + jj] + xg[u][3];

            float si = fsig(gi);
            float sf = fsig(gf);
            float so = fsig(go);
            float tg = ftanh_f(gg);

            float cN = sf * c_r[u] + si * tg;
            c_r[u] = cN;
            float hN = so * ftanh_f(cN);

            const int ci = b * Hd + jbase + jj;
            __nv_bfloat16 hi = __float2bfloat16_rn(hN);
            __nv_bfloat16 lo = __float2bfloat16_rn(hN - __bfloat162float(hi));
            stg_cg_u16(&g_hh[(t + 1) & 1][ci], *(uint16_t*)&hi);
            stg_cg_u16(&g_hl[(t + 1) & 1][ci], *(uint16_t*)&lo);
            const size_t hsi = ((size_t)b * Tt + t) * Hd + jbase + jj;
            stg_cg_u16(&g_hsh[hsi], *(uint16_t*)&hi);
            stg_cg_u16(&g_hsl[hsi], *(uint16_t*)&lo);
        }

        // pre-barrier prefetches (independent of h(t+1)):
        if (t + 1 < Tt) {
            #pragma unroll
            for (int g = 0; g < 4; g++) {
                xg[0][g] = g_xp[((size_t)ob0 * Tt + t + 1) * G4 + g * Hd + jbase + oj0];
                xg[1][g] = g_xp[((size_t)ob1 * Tt + t + 1) * G4 + g * Hd + jbase + oj1];
            }
            #pragma unroll
            for (int u = 0; u < 2; u++) {
                const int s = wk * 8 + u;
                BH0[u] = g_Bfh[BIDX(s, 0)]; BH1[u] = g_Bfh[BIDX(s, 1)];
                BL0[u] = g_Bfl[BIDX(s, 0)]; BL1[u] = g_Bfl[BIDX(s, 1)];
            }
        }

        // grid barrier: atomic arrive, single volatile-load poller
        __syncthreads();
        if (tid == 0) {
            __threadfence();
            atomicAdd(&g_bar, 1u);
            const unsigned tgt = (unsigned)(t + 1) * (unsigned)NBLK;
            while (*(volatile unsigned*)&g_bar < tgt) { }
            __threadfence();
        }
        __syncthreads();
    }
    #undef ISSUE_H
}

// ---------------------------------------------------------------------------
extern "C" void kernel_launch(void* const* d_in, const int* in_sizes, int n_in,
                              void* d_out, int out_size) {
    const float* xs = (const float*)d_in[0];
    const float* Wi = (const float*)d_in[1];
    const float* Wh = (const float*)d_in[2];
    const float* b  = (const float*)d_in[3];
    const float* Wo = (const float*)d_in[4];
    const float* bo = (const float*)d_in[5];
    float* out = (float*)d_out;

    float* xp_p = nullptr;
    __nv_bfloat16 *xsh_p = nullptr, *xsl_p = nullptr, *hsh_p = nullptr, *hsl_p = nullptr;
    uint4 *wifh = nullptr, *wifl = nullptr, *wofh = nullptr, *wofl = nullptr;
    cudaGetSymbolAddress((void**)&xp_p, g_xp);
    cudaGetSymbolAddress((void**)&xsh_p, g_xsh);
    cudaGetSymbolAddress((void**)&xsl_p, g_xsl);
    cudaGetSymbolAddress((void**)&hsh_p, g_hsh);
    cudaGetSymbolAddress((void**)&hsl_p, g_hsl);
    cudaGetSymbolAddress((void**)&wifh, g_WiFh);
    cudaGetSymbolAddress((void**)&wifl, g_WiFl);
    cudaGetSymbolAddress((void**)&wofh, g_WoFh);
    cudaGetSymbolAddress((void**)&wofl, g_WoFl);

    const int lp_smem = 196608;   // 3 x 64KB A buffers; Ds2 aliased into buf1
    cudaFuncSetAttribute(lstm_persist,
                         cudaFuncAttributeMaxDynamicSharedMemorySize, lp_smem);

    // 0) init + splits + fragment scatters
    zero_state<<<(Bb * Hd + 255) / 256, 256>>>();
    split_xs<<<(int)(((size_t)Mrows * INd + 255) / 256), 256>>>(xs);
    prep_Bfrag<<<(NBLK * NKS * 2 * 32) / 256, 256>>>(Wh);
    prep_Wfrag<<<(WI_CG * WI_KS * 32) / 256, 256>>>(Wi, G4, WI_KS, wifh, wifl);
    prep_Wfrag<<<(WO_CG * WO_KS * 32) / 256, 256>>>(Wo, OUTd, WO_KS, wofh, wofl);

    // 1) xp = xs @ Wi + b   (HMMA)
    {
        dim3 grid(G4 / 64, Mrows / 128);
        gemm_mma<INd><<<grid, 256>>>(xsh_p, xsl_p, wifh, wifl, b, xp_p, G4);
    }

    // 2) recurrence: one persistent launch
    lstm_persist<<<NBLK, 256, lp_smem>>>();

    // 3) logits = hs @ Wo + bo   (HMMA)
    {
        dim3 grid(OUTd / 64, Mrows / 128);
        gemm_mma<Hd><<<grid, 256>>>(hsh_p, hsl_p, wofh, wofl, bo, out, OUTd);
    }
}

// round 16
// speedup vs baseline: 1.1056x; 1.0182x over previous
#include <cuda_runtime.h>
#include <cuda_bf16.h>
#include <math.h>
#include <stdint.h>

#define Bb   64
#define Tt   256
#define INd  512
#define Hd   1024
#define OUTd 512
#define G4   (4*Hd)        // 4096
#define Mrows (Bb*Tt)      // 16384

#define NBLK 128           // persistent blocks; each owns 8 hidden cols (x4 gates = N=32)
#define NJJ  8             // hidden cols per block
#define NKS  64            // k16 steps (K=1024)

// ---------------- scratch (device globals) ----------------
__device__ float g_xp[(size_t)Mrows * G4];          // [B*T, 4H]
__device__ __nv_bfloat16 g_xsh[(size_t)Mrows * INd];  // xs hi split
__device__ __nv_bfloat16 g_xsl[(size_t)Mrows * INd];  // xs lo split
__device__ __nv_bfloat16 g_hsh[(size_t)Mrows * Hd]; // hs hi split
__device__ __nv_bfloat16 g_hsl[(size_t)Mrows * Hd]; // hs lo split
__device__ __nv_bfloat16 g_hh[2][Bb * Hd];          // h hi (ping-pong)
__device__ __nv_bfloat16 g_hl[2][Bb * Hd];          // h lo
__device__ unsigned g_bar;                          // grid barrier counter
// Wh pre-scattered into HMMA B-fragment order (recurrence):
__device__ uint4 g_Bfh[(size_t)NBLK * NKS * 2 * 32];
__device__ uint4 g_Bfl[(size_t)NBLK * NKS * 2 * 32];
// Wi / Wo fragment arrays
#define WI_CG (G4/32)      // 128
#define WI_KS (INd/16)     // 32
#define WO_CG (OUTd/32)    // 16
#define WO_KS (Hd/16)      // 64
__device__ uint4 g_WiFh[(size_t)WI_CG * WI_KS * 32 * 2];
__device__ uint4 g_WiFl[(size_t)WI_CG * WI_KS * 32 * 2];
__device__ uint4 g_WoFh[(size_t)WO_CG * WO_KS * 32 * 2];
__device__ uint4 g_WoFl[(size_t)WO_CG * WO_KS * 32 * 2];

#define SW128(b) ((b) ^ (((b) >> 3) & 0x70))
#define BIDX(s, wx) ((((size_t)blk * NKS + (s)) * 2 + (wx)) * 32 + lane)

__device__ __forceinline__ uint32_t smem_u32(const void* p) {
    uint32_t a;
    asm("{ .reg .u64 t; cvta.to.shared.u64 t, %1; cvt.u32.u64 %0, t; }" : "=r"(a) : "l"(p));
    return a;
}
__device__ __forceinline__ void ldmatrix_x4(uint32_t* r, uint32_t addr) {
    asm volatile("ldmatrix.sync.aligned.m8n8.x4.shared.b16 {%0,%1,%2,%3}, [%4];"
                 : "=r"(r[0]), "=r"(r[1]), "=r"(r[2]), "=r"(r[3]) : "r"(addr));
}
__device__ __forceinline__ void mma_bf16(float* c, const uint32_t* a,
                                         uint32_t b0, uint32_t b1) {
    asm volatile(
        "mma.sync.aligned.m16n8k16.row.col.f32.bf16.bf16.f32 "
        "{%0,%1,%2,%3}, {%4,%5,%6,%7}, {%8,%9}, {%0,%1,%2,%3};"
        : "+f"(c[0]), "+f"(c[1]), "+f"(c[2]), "+f"(c[3])
        : "r"(a[0]), "r"(a[1]), "r"(a[2]), "r"(a[3]), "r"(b0), "r"(b1));
}
__device__ __forceinline__ uint32_t pack_bf16(float x, float y) {
    __nv_bfloat162 v = __floats2bfloat162_rn(x, y);
    return *(uint32_t*)&v;
}
__device__ __forceinline__ void stg_cg_u16(void* p, uint16_t v) {
    asm volatile("st.global.cg.u16 [%0], %1;" :: "l"(p), "h"(v));
}
__device__ __forceinline__ float fsig(float x) {
    return __fdividef(1.f, 1.f + __expf(-x));
}
__device__ __forceinline__ float ftanh_f(float x) {
    return 1.f - __fdividef(2.f, __expf(2.f * x) + 1.f);
}
#define CP_ASYNC16(sm, gp) \
    asm volatile("cp.async.cg.shared.global [%0], [%1], 16;" :: "r"(sm), "l"(gp))
#define CP_COMMIT() asm volatile("cp.async.commit_group;" ::: "memory")
#define CP_WAIT(n)  asm volatile("cp.async.wait_group %0;" :: "n"(n) : "memory")

// ---------------------------------------------------------------------------
__global__ void zero_state() {
    int i = blockIdx.x * blockDim.x + threadIdx.x;
    if (i == 0) g_bar = 0;
    if (i < Bb * Hd) {
        g_hh[0][i] = __float2bfloat16(0.f);
        g_hl[0][i] = __float2bfloat16(0.f);
    }
}

__global__ __launch_bounds__(256) void split_xs(const float* __restrict__ xs) {
    size_t i = (size_t)blockIdx.x * blockDim.x + threadIdx.x;
    if (i < (size_t)Mrows * INd) {
        float v = xs[i];
        __nv_bfloat16 hi = __float2bfloat16_rn(v);
        g_xsh[i] = hi;
        g_xsl[i] = __float2bfloat16_rn(v - __bfloat162float(hi));
    }
}

// ---------------------------------------------------------------------------
__global__ __launch_bounds__(256) void prep_Bfrag(const float* __restrict__ Wh) {
    int gid = blockIdx.x * blockDim.x + threadIdx.x;
    int lane = gid & 31;
    int wx   = (gid >> 5) & 1;
    int ks   = (gid >> 6) & 63;
    int blk  = gid >> 12;

    uint32_t outh[4], outl[4];
    #pragma unroll
    for (int t2 = 0; t2 < 2; t2++) {
        int loc = wx * 16 + t2 * 8 + (lane >> 2);
        int g = loc >> 3, jj = loc & 7;
        int col = g * Hd + blk * NJJ + jj;
        int kb = ks * 16 + (lane & 3) * 2;
        float w0 = Wh[(size_t)(kb + 0) * G4 + col];
        float w1 = Wh[(size_t)(kb + 1) * G4 + col];
        float w8 = Wh[(size_t)(kb + 8) * G4 + col];
        float w9 = Wh[(size_t)(kb + 9) * G4 + col];
        float h0 = __bfloat162float(__float2bfloat16_rn(w0));
        float h1 = __bfloat162float(__float2bfloat16_rn(w1));
        float h8 = __bfloat162float(__float2bfloat16_rn(w8));
        float h9 = __bfloat162float(__float2bfloat16_rn(w9));
        outh[t2*2+0] = pack_bf16(h0, h1);
        outh[t2*2+1] = pack_bf16(h8, h9);
        outl[t2*2+0] = pack_bf16(w0 - h0, w1 - h1);
        outl[t2*2+1] = pack_bf16(w8 - h8, w9 - h9);
    }
    g_Bfh[gid] = make_uint4(outh[0], outh[1], outh[2], outh[3]);
    g_Bfl[gid] = make_uint4(outl[0], outl[1], outl[2], outl[3]);
}

// ---------------------------------------------------------------------------
__global__ __launch_bounds__(256)
void prep_Wfrag(const float* __restrict__ W, int N, int KS,
                uint4* __restrict__ outh_arr, uint4* __restrict__ outl_arr) {
    int gid = blockIdx.x * blockDim.x + threadIdx.x;
    int lane = gid & 31;
    int s    = (gid >> 5) % KS;
    int cg   = (gid >> 5) / KS;

    const int k0 = s * 16 + (lane & 3) * 2;
    #pragma unroll
    for (int j = 0; j < 2; j++) {
        uint32_t oh[4], ol[4];
        #pragma unroll
        for (int tt = 0; tt < 2; tt++) {
            int col = cg * 32 + (j * 2 + tt) * 8 + (lane >> 2);
            float w0 = W[(size_t)(k0 + 0) * N + col];
            float w1 = W[(size_t)(k0 + 1) * N + col];
            float w8 = W[(size_t)(k0 + 8) * N + col];
            float w9 = W[(size_t)(k0 + 9) * N + col];
            float h0 = __bfloat162float(__float2bfloat16_rn(w0));
            float h1 = __bfloat162float(__float2bfloat16_rn(w1));
            float h8 = __bfloat162float(__float2bfloat16_rn(w8));
            float h9 = __bfloat162float(__float2bfloat16_rn(w9));
            oh[tt*2+0] = pack_bf16(h0, h1);
            oh[tt*2+1] = pack_bf16(h8, h9);
            ol[tt*2+0] = pack_bf16(w0 - h0, w1 - h1);
            ol[tt*2+1] = pack_bf16(w8 - h8, w9 - h9);
        }
        outh_arr[(size_t)gid * 2 + j] = make_uint4(oh[0], oh[1], oh[2], oh[3]);
        outl_arr[(size_t)gid * 2 + j] = make_uint4(ol[0], ol[1], ol[2], ol[3]);
    }
}

// ---------------------------------------------------------------------------
// bf16x3-split HMMA GEMM (unchanged; projections).
template<int K>
__global__ __launch_bounds__(256)
void gemm_mma(const __nv_bfloat16* __restrict__ Ah,
              const __nv_bfloat16* __restrict__ Al,
              const uint4* __restrict__ BfH, const uint4* __restrict__ BfL,
              const float* __restrict__ bias, float* __restrict__ C, int N) {
    constexpr int KS = K / 16;
    constexpr int NC = K / 64;
    __shared__ __align__(16) char smA[2][2][16384];

    const int tid  = threadIdx.x;
    const int lane = tid & 31;
    const int wid  = tid >> 5;
    const int wy   = wid & 3;
    const int wn   = wid >> 2;
    const int rowBase = blockIdx.y * 128;
    const int colBase = blockIdx.x * 64;
    const int cg = blockIdx.x * 2 + wn;

    const uint32_t uA[2][2] = {
        { smem_u32(smA[0][0]), smem_u32(smA[0][1]) },
        { smem_u32(smA[1][0]), smem_u32(smA[1][1]) } };

    int rowi[4], qi[4]; uint32_t offi[4];
    #pragma unroll
    for (int i = 0; i < 4; i++) {
        int idx = i * 256 + tid;
        rowi[i] = idx >> 3; qi[i] = idx & 7;
        offi[i] = SW128((uint32_t)(rowi[i] * 128 + qi[i] * 16));
    }
    #define ISSUE_A(buf, kb)                                                     \
        do {                                                                     \
            _Pragma("unroll")                                                    \
            for (int i = 0; i < 4; i++) {                                        \
                CP_ASYNC16(uA[buf][0] + offi[i],                                 \
                    &Ah[(size_t)(rowBase + rowi[i]) * K + (kb) + qi[i] * 8]);    \
                CP_ASYNC16(uA[buf][1] + offi[i],                                 \
                    &Al[(size_t)(rowBase + rowi[i]) * K + (kb) + qi[i] * 8]);    \
            }                                                                    \
            CP_COMMIT();                                                         \
        } while (0)

    float acc[2][4][4] = {};
    const int lr = lane & 15, lch = (lane >> 4) * 8;

    const size_t bbase = ((size_t)cg * KS) * 64 + lane * 2;
    uint4 BH[2][2], BL[2][2];
    #pragma unroll
    for (int s = 0; s < 2; s++) {
        BH[s][0] = BfH[bbase + s * 64 + 0];
        BH[s][1] = BfH[bbase + s * 64 + 1];
        BL[s][0] = BfL[bbase + s * 64 + 0];
        BL[s][1] = BfL[bbase + s * 64 + 1];
    }

    ISSUE_A(0, 0);

    for (int kc = 0; kc < NC; kc++) {
        if (kc + 1 < NC) { ISSUE_A((kc + 1) & 1, (kc + 1) * 64); CP_WAIT(1); }
        else             { CP_WAIT(0); }
        __syncthreads();

        const uint32_t uh = uA[kc & 1][0], ul = uA[kc & 1][1];
        #pragma unroll
        for (int ks = 0; ks < 4; ks++) {
            const int s = kc * 4 + ks;
            uint4 bh0 = BH[ks & 1][0], bh1 = BH[ks & 1][1];
            uint4 bl0 = BL[ks & 1][0], bl1 = BL[ks & 1][1];
            if (s + 2 < KS) {
                BH[ks & 1][0] = BfH[bbase + (size_t)(s + 2) * 64 + 0];
                BH[ks & 1][1] = BfH[bbase + (size_t)(s + 2) * 64 + 1];
                BL[ks & 1][0] = BfL[bbase + (size_t)(s + 2) * 64 + 0];
                BL[ks & 1][1] = BfL[bbase + (size_t)(s + 2) * 64 + 1];
            }
            #pragma unroll
            for (int mt = 0; mt < 2; mt++) {
                const int lrow = wy * 32 + mt * 16 + lr;
                uint32_t offA = SW128((uint32_t)(lrow * 128 + (ks * 16 + lch) * 2));
                uint32_t ah[4], al[4];
                ldmatrix_x4(ah, uh + offA);
                ldmatrix_x4(al, ul + offA);

                mma_bf16(acc[mt][0], ah, bh0.x, bh0.y);
                mma_bf16(acc[mt][1], ah, bh0.z, bh0.w);
                mma_bf16(acc[mt][2], ah, bh1.x, bh1.y);
                mma_bf16(acc[mt][3], ah, bh1.z, bh1.w);
                mma_bf16(acc[mt][0], al, bh0.x, bh0.y);
                mma_bf16(acc[mt][1], al, bh0.z, bh0.w);
                mma_bf16(acc[mt][2], al, bh1.x, bh1.y);
                mma_bf16(acc[mt][3], al, bh1.z, bh1.w);
                mma_bf16(acc[mt][0], ah, bl0.x, bl0.y);
                mma_bf16(acc[mt][1], ah, bl0.z, bl0.w);
                mma_bf16(acc[mt][2], ah, bl1.x, bl1.y);
                mma_bf16(acc[mt][3], ah, bl1.z, bl1.w);
            }
        }
        __syncthreads();
    }

    const int r = lane >> 2, cc = (lane & 3) * 2;
    #pragma unroll
    for (int mt = 0; mt < 2; mt++) {
        const int m = rowBase + wy * 32 + mt * 16 + r;
        #pragma unroll
        for (int nt = 0; nt < 4; nt++) {
            const int n = colBase + wn * 32 + nt * 8 + cc;
            float b0 = bias[n], b1 = bias[n + 1];
            *(float2*)&C[(size_t)m * N + n] =
                make_float2(acc[mt][nt][0] + b0, acc[mt][nt][1] + b1);
            *(float2*)&C[(size_t)(m + 8) * N + n] =
                make_float2(acc[mt][nt][2] + b0, acc[mt][nt][3] + b1);
        }
    }
    #undef ISSUE_A
}

// ---------------------------------------------------------------------------
// Persistent HMMA LSTM v10: K=256 chunks (4/step, 3 x 64KB buffers), with the
// two split-K halves DECOUPLED: each 128-thread wk-half stages and consumes
// only its own 2 panels per buffer, synced by a named barrier (bar.sync 1/2).
// Ds2 gets dedicated smem (no aliasing; safe under half drift). One full
// __syncthreads before the epilogue; counter grid barrier unchanged.
__global__ __launch_bounds__(256)
void lstm_persist() {
    extern __shared__ char dyn_sm[];
    // A: [buf3][split2][4 panels x 8192B] = 196608 B; Ds2: 16384 B dedicated.
    float (*Ds2)[64][32] = (float (*)[64][32])(dyn_sm + 196608);

    const int tid = threadIdx.x;
    const int lane = tid & 31;
    const int wid = tid >> 5;
    const int wy = wid & 3;          // M tile
    const int wk = wid >> 2;         // K half (2 panels of each chunk)
    const int lt  = tid & 127;       // thread id within wk-half
    const int blk = blockIdx.x;
    const int jbase = blk * NJJ;

    const int lrow = wy * 16 + (lane & 15);
    const int lch  = (lane >> 4) * 8;

    // per-half named barrier (128 threads each)
    #define WKSYNC() asm volatile("bar.sync %0, 128;" :: "r"(1 + wk) : "memory")

    // A staging, wk-local: half stages its 2 panels x 2 splits = 2048 uint4
    // over 128 threads -> 8 per split per thread.
    uint32_t off_sm[8]; int off_g[8];
    #pragma unroll
    for (int i = 0; i < 8; i++) {
        int idx = i * 128 + lt;           // 0..1023
        int pl  = idx >> 9;               // panel-local 0/1
        int inner = idx & 511;
        int row = inner >> 3, q = inner & 7;
        int panel = wk * 2 + pl;
        off_sm[i] = (uint32_t)(panel * 8192) + SW128((uint32_t)(row * 128 + q * 16));
        off_g[i]  = row * Hd + panel * 64 + q * 8;
    }

    uint32_t uB[3][2];  // [buf][split] base
    #pragma unroll
    for (int bu = 0; bu < 3; bu++)
        #pragma unroll
        for (int sp = 0; sp < 2; sp++)
            uB[bu][sp] = smem_u32(dyn_sm + bu * 65536 + sp * 32768);

    #define ISSUE_H(buf, kb)                                                     \
        do {                                                                     \
            _Pragma("unroll")                                                    \
            for (int i = 0; i < 8; i++) {                                        \
                CP_ASYNC16(uB[buf][0] + off_sm[i], &hh[off_g[i] + (kb)]);        \
                CP_ASYNC16(uB[buf][1] + off_sm[i], &hl[off_g[i] + (kb)]);        \
            }                                                                    \
            CP_COMMIT();                                                         \
        } while (0)

    const int ob0 = (tid * 2) >> 3,     oj0 = (tid * 2) & 7;
    const int ob1 = (tid * 2 + 1) >> 3, oj1 = (tid * 2 + 1) & 7;
    float c_r[2] = {0.f, 0.f};

    // prefetch xp for step 0
    float xg[2][4];
    #pragma unroll
    for (int g = 0; g < 4; g++) {
        xg[0][g] = g_xp[((size_t)ob0 * Tt + 0) * G4 + g * Hd + jbase + oj0];
        xg[1][g] = g_xp[((size_t)ob1 * Tt + 0) * G4 + g * Hd + jbase + oj1];
    }

    // B ring (2-deep); per-warp iteration u = c*8 + j,
    // s(u) = (u>>3)*16 + wk*8 + (u&7).
    uint4 BH0[2], BH1[2], BL0[2], BL1[2];
    #pragma unroll
    for (int u = 0; u < 2; u++) {
        const int s = wk * 8 + u;
        BH0[u] = g_Bfh[BIDX(s, 0)]; BH1[u] = g_Bfh[BIDX(s, 1)];
        BL0[u] = g_Bfl[BIDX(s, 0)]; BL1[u] = g_Bfl[BIDX(s, 1)];
    }

    for (int t = 0; t < Tt; t++) {
        const __nv_bfloat16* hh = g_hh[t & 1];
        const __nv_bfloat16* hl = g_hl[t & 1];

        // stage chunks 0 and 1 (this half's panels only)
        ISSUE_H(0, 0);
        ISSUE_H(1, 256);
        CP_WAIT(1);            // chunk 0 done (this thread's loads)
        WKSYNC();              // whole half's loads visible

        float acc[4][4] = {};   // [n-tile][frag]

        #pragma unroll
        for (int c = 0; c < 4; c++) {
            if (c + 2 < 4) ISSUE_H((c + 2) % 3, (c + 2) * 256);

            const uint32_t uh = uB[c % 3][0] + (uint32_t)(wk * 16384);
            const uint32_t ul = uB[c % 3][1] + (uint32_t)(wk * 16384);

            #pragma unroll
            for (int j = 0; j < 8; j++) {
                const int u = c * 8 + j;
                uint4 bh0 = BH0[u & 1], bh1 = BH1[u & 1];
                uint4 bl0 = BL0[u & 1], bl1 = BL1[u & 1];
                if (u + 2 < 32) {
                    const int s2 = ((u + 2) >> 3) * 16 + wk * 8 + ((u + 2) & 7);
                    BH0[u & 1] = g_Bfh[BIDX(s2, 0)];
                    BH1[u & 1] = g_Bfh[BIDX(s2, 1)];
                    BL0[u & 1] = g_Bfl[BIDX(s2, 0)];
                    BL1[u & 1] = g_Bfl[BIDX(s2, 1)];
                }
                uint32_t offA = (uint32_t)((j >> 2) * 8192)
                              + SW128((uint32_t)(lrow * 128 + ((j & 3) * 16 + lch) * 2));
                uint32_t ah[4], al[4];
                ldmatrix_x4(ah, uh + offA);
                ldmatrix_x4(al, ul + offA);

                mma_bf16(acc[0], ah, bh0.x, bh0.y);
                mma_bf16(acc[1], ah, bh0.z, bh0.w);
                mma_bf16(acc[2], ah, bh1.x, bh1.y);
                mma_bf16(acc[3], ah, bh1.z, bh1.w);
                mma_bf16(acc[0], al, bh0.x, bh0.y);
                mma_bf16(acc[1], al, bh0.z, bh0.w);
                mma_bf16(acc[2], al, bh1.x, bh1.y);
                mma_bf16(acc[3], al, bh1.z, bh1.w);
                mma_bf16(acc[0], ah, bl0.x, bl0.y);
                mma_bf16(acc[1], ah, bl0.z, bl0.w);
                mma_bf16(acc[2], ah, bl1.x, bl1.y);
                mma_bf16(acc[3], ah, bl1.z, bl1.w);
            }

            if (c + 1 < 4) {
                if (c + 2 < 4) CP_WAIT(1);    // oldest pending (c+1) done
                else           CP_WAIT(0);
                WKSYNC();
            }
        }

        // each half writes its own dedicated Ds2 plane (no cross-half hazard)
        const int r = lane >> 2, cc = (lane & 3) * 2;
        const int m0 = wy * 16;
        #pragma unroll
        for (int nt = 0; nt < 4; nt++) {
            Ds2[wk][m0 + r    ][nt * 8 + cc    ] = acc[nt][0];
            Ds2[wk][m0 + r    ][nt * 8 + cc + 1] = acc[nt][1];
            Ds2[wk][m0 + r + 8][nt * 8 + cc    ] = acc[nt][2];
            Ds2[wk][m0 + r + 8][nt * 8 + cc + 1] = acc[nt][3];
        }
        __syncthreads();   // join halves: both Ds2 planes complete

        // fused nonlinearity (xg prefetched, fast intrinsics); st.cg stores
        #pragma unroll
        for (int u = 0; u < 2; u++) {
            const int b  = u ? ob1 : ob0;
            const int jj = u ? oj1 : oj0;
            float gi = Ds2[0][b][0*8 + jj] + Ds2[1][b][0*8 + jj] + xg[u][0];
            float gf = Ds2[0][b][1*8 + jj] + Ds2[1][b][1*8 + jj] + xg[u][1];
            float gg = Ds2[0][b][2*8 + jj] + Ds2[1][b][2*8 + jj] + xg[u][2];
            float go = Ds2[0][b][3*8 + jj] + Ds2[1][b][3*8 + jj] + xg[u][3];

            float si = fsig(gi);
            float sf = fsig(gf);
            float so = fsig(go);
            float tg = ftanh_f(gg);

            float cN = sf * c_r[u] + si * tg;
            c_r[u] = cN;
            float hN = so * ftanh_f(cN);

            const int ci = b * Hd + jbase + jj;
            __nv_bfloat16 hi = __float2bfloat16_rn(hN);
            __nv_bfloat16 lo = __float2bfloat16_rn(hN - __bfloat162float(hi));
            stg_cg_u16(&g_hh[(t + 1) & 1][ci], *(uint16_t*)&hi);
            stg_cg_u16(&g_hl[(t + 1) & 1][ci], *(uint16_t*)&lo);
            const size_t hsi = ((size_t)b * Tt + t) * Hd + jbase + jj;
            stg_cg_u16(&g_hsh[hsi], *(uint16_t*)&hi);
            stg_cg_u16(&g_hsl[hsi], *(uint16_t*)&lo);
        }

        // pre-barrier prefetches (independent of h(t+1)):
        if (t + 1 < Tt) {
            #pragma unroll
            for (int g = 0; g < 4; g++) {
                xg[0][g] = g_xp[((size_t)ob0 * Tt + t + 1) * G4 + g * Hd + jbase + oj0];
                xg[1][g] = g_xp[((size_t)ob1 * Tt + t + 1) * G4 + g * Hd + jbase + oj1];
            }
            #pragma unroll
            for (int u = 0; u < 2; u++) {
                const int s = wk * 8 + u;
                BH0[u] = g_Bfh[BIDX(s, 0)]; BH1[u] = g_Bfh[BIDX(s, 1)];
                BL0[u] = g_Bfl[BIDX(s, 0)]; BL1[u] = g_Bfl[BIDX(s, 1)];
            }
        }

        // grid barrier: atomic arrive, single volatile-load poller
        __syncthreads();
        if (tid == 0) {
            __threadfence();
            atomicAdd(&g_bar, 1u);
            const unsigned tgt = (unsigned)(t + 1) * (unsigned)NBLK;
            while (*(volatile unsigned*)&g_bar < tgt) { }
            __threadfence();
        }
        __syncthreads();
    }
    #undef ISSUE_H
    #undef WKSYNC
}

// ---------------------------------------------------------------------------
extern "C" void kernel_launch(void* const* d_in, const int* in_sizes, int n_in,
                              void* d_out, int out_size) {
    const float* xs = (const float*)d_in[0];
    const float* Wi = (const float*)d_in[1];
    const float* Wh = (const float*)d_in[2];
    const float* b  = (const float*)d_in[3];
    const float* Wo = (const float*)d_in[4];
    const float* bo = (const float*)d_in[5];
    float* out = (float*)d_out;

    float* xp_p = nullptr;
    __nv_bfloat16 *xsh_p = nullptr, *xsl_p = nullptr, *hsh_p = nullptr, *hsl_p = nullptr;
    uint4 *wifh = nullptr, *wifl = nullptr, *wofh = nullptr, *wofl = nullptr;
    cudaGetSymbolAddress((void**)&xp_p, g_xp);
    cudaGetSymbolAddress((void**)&xsh_p, g_xsh);
    cudaGetSymbolAddress((void**)&xsl_p, g_xsl);
    cudaGetSymbolAddress((void**)&hsh_p, g_hsh);
    cudaGetSymbolAddress((void**)&hsl_p, g_hsl);
    cudaGetSymbolAddress((void**)&wifh, g_WiFh);
    cudaGetSymbolAddress((void**)&wifl, g_WiFl);
    cudaGetSymbolAddress((void**)&wofh, g_WoFh);
    cudaGetSymbolAddress((void**)&wofl, g_WoFl);

    const int lp_smem = 196608 + 16384;   // 3 x 64KB A buffers + dedicated Ds2
    cudaFuncSetAttribute(lstm_persist,
                         cudaFuncAttributeMaxDynamicSharedMemorySize, lp_smem);

    // 0) init + splits + fragment scatters
    zero_state<<<(Bb * Hd + 255) / 256, 256>>>();
    split_xs<<<(int)(((size_t)Mrows * INd + 255) / 256), 256>>>(xs);
    prep_Bfrag<<<(NBLK * NKS * 2 * 32) / 256, 256>>>(Wh);
    prep_Wfrag<<<(WI_CG * WI_KS * 32) / 256, 256>>>(Wi, G4, WI_KS, wifh, wifl);
    prep_Wfrag<<<(WO_CG * WO_KS * 32) / 256, 256>>>(Wo, OUTd, WO_KS, wofh, wofl);

    // 1) xp = xs @ Wi + b   (HMMA)
    {
        dim3 grid(G4 / 64, Mrows / 128);
        gemm_mma<INd><<<grid, 256>>>(xsh_p, xsl_p, wifh, wifl, b, xp_p, G4);
    }

    // 2) recurrence: one persistent launch
    lstm_persist<<<NBLK, 256, lp_smem>>>();

    // 3) logits = hs @ Wo + bo   (HMMA)
    {
        dim3 grid(OUTd / 64, Mrows / 128);
        gemm_mma<Hd><<<grid, 256>>>(hsh_p, hsl_p, wofh, wofl, bo, out, OUTd);
    }
}